// round 5
// baseline (speedup 1.0000x reference)
#include <cuda_runtime.h>
#include <cuda_bf16.h>

#define MAX_NODES 50000
#define MAX_E     800000
#define F 128
#define SCAN_BLKS ((MAX_NODES + 255) / 256)   // 196

// Scratch (device globals; allocation-free per harness rules)
__device__ float g_h[MAX_NODES * F];
__device__ float g_stats[2 * F];       // [0:128) sum, [128:256) sumsq
__device__ float g_W2p[F * F];
__device__ float g_b2p[F];
__device__ int   g_src[MAX_E];
__device__ int   g_dst[MAX_E];
__device__ int   g_cnt[MAX_NODES];
__device__ int   g_off[MAX_NODES + 1];
__device__ int   g_pos[MAX_NODES];
__device__ int   g_csr[MAX_E];
__device__ int   g_bsum[SCAN_BLKS + 1];
__device__ int   g_boff[SCAN_BLKS + 1];
__device__ int   g_is64;

// packed f32x2 FMA: d = a*b + d  (even/odd K partial sums)
__device__ __forceinline__ void ffma2(unsigned long long& d,
                                      unsigned long long a,
                                      unsigned long long b) {
    asm("fma.rn.f32x2 %0, %1, %2, %0;" : "+l"(d) : "l"(a), "l"(b));
}
__device__ __forceinline__ float f2sum(unsigned long long p) {
    float lo = __int_as_float((int)(unsigned)(p & 0xffffffffull));
    float hi = __int_as_float((int)(unsigned)(p >> 32));
    return lo + hi;
}

// ---------------------------------------------------------------------------
// detect: edge_index int64 (all odd 32-bit words zero) vs int32
// ---------------------------------------------------------------------------
__global__ void detect_kernel(const int* __restrict__ ei, int n_words) {
    int nz = 0;
    for (int i = threadIdx.x; i < 2048; i += 32) {
        int w = 2 * i + 1;
        if (w < n_words && ei[w] != 0) nz = 1;
    }
    nz = __any_sync(0xffffffffu, nz);
    if (threadIdx.x == 0) g_is64 = nz ? 0 : 1;
}

// ---------------------------------------------------------------------------
// zero: counters + BN stats (must run every graph replay)
// ---------------------------------------------------------------------------
__global__ void zero_kernel(int n_nodes) {
    int i = blockIdx.x * blockDim.x + threadIdx.x;
    if (i < n_nodes) g_cnt[i] = 0;
    if (i < 2 * F) g_stats[i] = 0.0f;
}

// ---------------------------------------------------------------------------
// convert: unpack indices (guarded) + histogram counts per dst
// ---------------------------------------------------------------------------
__global__ void convert_kernel(const void* __restrict__ eiv, int n_edges,
                               int n_nodes) {
    int e = blockIdx.x * blockDim.x + threadIdx.x;
    if (e >= n_edges) return;
    long long s, d;
    if (g_is64) {
        const long long* ei = (const long long*)eiv;
        s = ei[e];
        d = ei[n_edges + e];
    } else {
        const int* ei = (const int*)eiv;
        s = ei[e];
        d = ei[n_edges + e];
    }
    bool ok = (s >= 0 && s < n_nodes && d >= 0 && d < n_nodes);
    g_src[e] = ok ? (int)s : -1;
    g_dst[e] = ok ? (int)d : -1;
    if (ok) atomicAdd(&g_cnt[(int)d], 1);
}

// ---------------------------------------------------------------------------
// 3-phase grid-wide exclusive scan of g_cnt -> g_off / g_pos
// ---------------------------------------------------------------------------
__global__ void scan1_kernel(int n_nodes) {
    __shared__ int sm[256];
    int t = threadIdx.x;
    int i = blockIdx.x * 256 + t;
    int c = (i < n_nodes) ? g_cnt[i] : 0;
    sm[t] = c;
    __syncthreads();
#pragma unroll
    for (int off = 1; off < 256; off <<= 1) {
        int add = (t >= off) ? sm[t - off] : 0;
        __syncthreads();
        sm[t] += add;
        __syncthreads();
    }
    if (i < n_nodes) g_off[i] = sm[t] - c;       // exclusive within block
    if (t == 255) g_bsum[blockIdx.x] = sm[255];  // block total
}

__global__ void scan2_kernel(int n_blks) {
    __shared__ int sm[256];
    int t = threadIdx.x;
    int v = (t < n_blks) ? g_bsum[t] : 0;
    sm[t] = v;
    __syncthreads();
#pragma unroll
    for (int off = 1; off < 256; off <<= 1) {
        int add = (t >= off) ? sm[t - off] : 0;
        __syncthreads();
        sm[t] += add;
        __syncthreads();
    }
    if (t < n_blks) g_boff[t] = sm[t] - v;       // exclusive block offset
    if (t == n_blks - 1) g_boff[n_blks] = sm[t]; // grand total
}

__global__ void scan3_kernel(int n_nodes) {
    int i = blockIdx.x * 256 + threadIdx.x;
    if (i < n_nodes) {
        int o = g_off[i] + g_boff[blockIdx.x];
        g_off[i] = o;
        g_pos[i] = o;
    }
    if (i == n_nodes - 1)
        g_off[n_nodes] = g_boff[gridDim.x];      // total edge count
}

// ---------------------------------------------------------------------------
// fill: bucket sources by destination
// ---------------------------------------------------------------------------
__global__ void fill_kernel(int n_edges) {
    int e = blockIdx.x * blockDim.x + threadIdx.x;
    if (e >= n_edges) return;
    int s = g_src[e], d = g_dst[e];
    if (s < 0 || d < 0) return;
    int p = atomicAdd(&g_pos[d], 1);
    g_csr[p] = s;
}

// ---------------------------------------------------------------------------
// GEMM: out[m][n] = act( sum_k A[m][k] * W[n][k] + bias[n] )
// Mainloop uses packed fma.rn.f32x2 along K (even/odd partial sums).
// FIRST: A-tile gathered on the fly (agg = x[m] + sum_{CSR[m]} x[src]),
//        ReLU + BN-stat accumulation, out = g_h.
// else:  A = g_h, W = g_W2p (BN-folded), out = d_out.
// ---------------------------------------------------------------------------
#define PITCH 132
#define GEMM_SMEM ((64 + 128) * PITCH * 4)

__device__ __forceinline__ void f4add(float4& a, const float4& b) {
    a.x += b.x; a.y += b.y; a.z += b.z; a.w += b.w;
}

template <bool FIRST>
__global__ void __launch_bounds__(256, 2)
gemm_kernel(const float* __restrict__ Xp, const float* __restrict__ Wp,
            const float* __restrict__ biasp, float* __restrict__ outp, int M) {
    extern __shared__ float smem[];
    float* As = smem;               // 64 x PITCH
    float* Ws = smem + 64 * PITCH;  // 128 x PITCH

    const float* W    = FIRST ? Wp    : g_W2p;
    const float* bias = FIRST ? biasp : g_b2p;
    float* out        = FIRST ? g_h   : outp;

    int tid = threadIdx.x;
    int m0 = blockIdx.x * 64;
    int tx = tid & 31, ty = tid >> 5;

    // Load W (128x128), coalesced float4, store pitch-132
#pragma unroll
    for (int p = 0; p < 16; p++) {
        int idx = tid + p * 256;            // float4 index
        int r = idx >> 5, c4 = idx & 31;
        float4 v = ((const float4*)W)[idx];
        *(float4*)&Ws[r * PITCH + c4 * 4] = v;
    }

    if (FIRST) {
        // Gather-aggregate: warp ty owns rows m0+ty*8 .. +7
        const float4* x4 = (const float4*)Xp;
#pragma unroll 1
        for (int i = 0; i < 8; i++) {
            int r = ty * 8 + i;
            int m = m0 + r;
            float4 a0 = make_float4(0.f, 0.f, 0.f, 0.f);
            float4 a1 = a0, a2 = a0, a3 = a0;
            if (m < M) {
                a0 = __ldg(&x4[(size_t)m * 32 + tx]);   // self term
                int e = g_off[m], e1 = g_off[m + 1];
                for (; e + 3 < e1; e += 4) {
                    int s0 = g_csr[e], s1 = g_csr[e + 1];
                    int s2 = g_csr[e + 2], s3 = g_csr[e + 3];
                    float4 v0 = __ldg(&x4[(size_t)s0 * 32 + tx]);
                    float4 v1 = __ldg(&x4[(size_t)s1 * 32 + tx]);
                    float4 v2 = __ldg(&x4[(size_t)s2 * 32 + tx]);
                    float4 v3 = __ldg(&x4[(size_t)s3 * 32 + tx]);
                    f4add(a0, v0); f4add(a1, v1); f4add(a2, v2); f4add(a3, v3);
                }
                for (; e < e1; e++) {
                    int s0 = g_csr[e];
                    f4add(a1, __ldg(&x4[(size_t)s0 * 32 + tx]));
                }
                f4add(a0, a1); f4add(a2, a3); f4add(a0, a2);
            }
            *(float4*)&As[r * PITCH + tx * 4] = a0;
        }
    } else {
        // Load A tile (64x128) from g_h
#pragma unroll
        for (int p = 0; p < 8; p++) {
            int idx = tid + p * 256;
            int r = idx >> 5, c4 = idx & 31;
            int m = m0 + r;
            float4 v = make_float4(0.f, 0.f, 0.f, 0.f);
            if (m < M) v = ((const float4*)g_h)[(size_t)m * 32 + c4];
            *(float4*)&As[r * PITCH + c4 * 4] = v;
        }
    }
    __syncthreads();

    // Accumulators: f32x2 packed {even-k partial, odd-k partial}
    unsigned long long acc[8][4];
#pragma unroll
    for (int i = 0; i < 8; i++)
#pragma unroll
        for (int j = 0; j < 4; j++) acc[i][j] = 0ull;

#pragma unroll 4
    for (int k4 = 0; k4 < 32; k4++) {
        ulonglong2 wv[4];   // {k,k+1} in .x, {k+2,k+3} in .y
#pragma unroll
        for (int j = 0; j < 4; j++)
            wv[j] = *(const ulonglong2*)&Ws[(tx + 32 * j) * PITCH + k4 * 4];
#pragma unroll
        for (int i = 0; i < 8; i++) {
            ulonglong2 av =
                *(const ulonglong2*)&As[(ty * 8 + i) * PITCH + k4 * 4];
#pragma unroll
            for (int j = 0; j < 4; j++) {
                ffma2(acc[i][j], av.x, wv[j].x);
                ffma2(acc[i][j], av.y, wv[j].y);
            }
        }
    }
    __syncthreads();  // smem reused below for stats reduction

    float b[4];
#pragma unroll
    for (int j = 0; j < 4; j++) b[j] = bias[tx + 32 * j];

    float colS[4] = {0.f, 0.f, 0.f, 0.f};
    float colQ[4] = {0.f, 0.f, 0.f, 0.f};
#pragma unroll
    for (int i = 0; i < 8; i++) {
        int m = m0 + ty * 8 + i;
        if (m < M) {
#pragma unroll
            for (int j = 0; j < 4; j++) {
                float v = f2sum(acc[i][j]) + b[j];
                if (FIRST) v = fmaxf(v, 0.0f);
                out[(size_t)m * F + tx + 32 * j] = v;
                if (FIRST) { colS[j] += v; colQ[j] += v * v; }
            }
        }
    }

    if (FIRST) {
        float* redS = smem;          // 8 x 128
        float* redQ = smem + 1024;   // 8 x 128
#pragma unroll
        for (int j = 0; j < 4; j++) {
            redS[ty * F + tx + 32 * j] = colS[j];
            redQ[ty * F + tx + 32 * j] = colQ[j];
        }
        __syncthreads();
        if (tid < F) {
            float s = 0.f;
#pragma unroll
            for (int t = 0; t < 8; t++) s += redS[t * F + tid];
            atomicAdd(&g_stats[tid], s);
        } else {
            int c = tid - F;
            float q = 0.f;
#pragma unroll
            for (int t = 0; t < 8; t++) q += redQ[t * F + c];
            atomicAdd(&g_stats[F + c], q);
        }
    }
}

// ---------------------------------------------------------------------------
// fold BN into W2/b2:  s = gamma*rsqrt(var+eps), t = beta - mean*s
//     W2p[o][k] = W2[o][k]*s[k];  b2p[o] = b2[o] + sum_k W2[o][k]*t[k]
// ---------------------------------------------------------------------------
__global__ void fold_kernel(const float* __restrict__ gamma,
                            const float* __restrict__ beta,
                            const float* __restrict__ W2,
                            const float* __restrict__ b2, float invM) {
    __shared__ float sc[F], tc[F];
    int t = threadIdx.x;  // 128 threads
    float S = g_stats[t], Q = g_stats[F + t];
    float mean = S * invM;
    float var = Q * invM - mean * mean;
    float s = gamma[t] * rsqrtf(var + 1e-5f);
    sc[t] = s;
    tc[t] = beta[t] - mean * s;
    __syncthreads();
    float acc = b2[t];
#pragma unroll
    for (int k = 0; k < F; k++) {
        float w = W2[t * F + k];
        g_W2p[t * F + k] = w * sc[k];
        acc += w * tc[k];
    }
    g_b2p[t] = acc;
}

// ---------------------------------------------------------------------------
extern "C" void kernel_launch(void* const* d_in, const int* in_sizes, int n_in,
                              void* d_out, int out_size) {
    const float* x         = (const float*)d_in[0];
    const void*  ei        = (const void*)d_in[1];
    const float* W1        = (const float*)d_in[2];
    const float* b1        = (const float*)d_in[3];
    const float* gamma     = (const float*)d_in[4];
    const float* beta      = (const float*)d_in[5];
    const float* W2        = (const float*)d_in[6];
    const float* b2        = (const float*)d_in[7];
    float* out             = (float*)d_out;

    int n_nodes = in_sizes[0] / F;
    int n_edges = in_sizes[1] / 2;

    cudaFuncSetAttribute(gemm_kernel<true>,
                         cudaFuncAttributeMaxDynamicSharedMemorySize, GEMM_SMEM);
    cudaFuncSetAttribute(gemm_kernel<false>,
                         cudaFuncAttributeMaxDynamicSharedMemorySize, GEMM_SMEM);

    int sblks = (n_nodes + 255) / 256;

    detect_kernel<<<1, 32>>>((const int*)ei, in_sizes[1]);
    zero_kernel<<<sblks, 256>>>(n_nodes);
    convert_kernel<<<(n_edges + 255) / 256, 256>>>(ei, n_edges, n_nodes);
    scan1_kernel<<<sblks, 256>>>(n_nodes);
    scan2_kernel<<<1, 256>>>(sblks);
    scan3_kernel<<<sblks, 256>>>(n_nodes);
    fill_kernel<<<(n_edges + 255) / 256, 256>>>(n_edges);

    int gb = (n_nodes + 63) / 64;
    gemm_kernel<true><<<gb, 256, GEMM_SMEM>>>(x, W1, b1, nullptr, n_nodes);
    fold_kernel<<<1, F>>>(gamma, beta, W2, b2, 1.0f / (float)n_nodes);
    gemm_kernel<false><<<gb, 256, GEMM_SMEM>>>(nullptr, nullptr, nullptr, out,
                                               n_nodes);
}

// round 6
// speedup vs baseline: 1.0857x; 1.0857x over previous
#include <cuda_runtime.h>
#include <cuda_bf16.h>

#define MAX_NODES 50000
#define MAX_E     800000
#define F 128
#define DEG_CAP   64
#define SPILL_CAP 65536

// Scratch (device globals; allocation-free per harness rules)
__device__ float g_h[MAX_NODES * F];
__device__ float g_stats[2 * F];       // [0:128) sum, [128:256) sumsq
__device__ float g_sc[F];              // BN scale folded into W2 columns
__device__ float g_b2p[F];             // BN-folded bias for layer 2
__device__ int   g_cnt[MAX_NODES];     // degree per dst
__device__ int   g_csrp[MAX_NODES * DEG_CAP];  // padded CSR (12.8 MB)
__device__ int   g_spill[2 * SPILL_CAP];
__device__ int   g_nspill;
__device__ int   g_is64;

// packed f32x2 FMA: d = a*b + d  (even/odd K partial sums)
__device__ __forceinline__ void ffma2(unsigned long long& d,
                                      unsigned long long a,
                                      unsigned long long b) {
    asm("fma.rn.f32x2 %0, %1, %2, %0;" : "+l"(d) : "l"(a), "l"(b));
}
__device__ __forceinline__ float f2sum(unsigned long long p) {
    float lo = __int_as_float((int)(unsigned)(p & 0xffffffffull));
    float hi = __int_as_float((int)(unsigned)(p >> 32));
    return lo + hi;
}

// ---------------------------------------------------------------------------
// detect: edge_index int64 (all odd 32-bit words zero) vs int32
// ---------------------------------------------------------------------------
__global__ void detect_kernel(const int* __restrict__ ei, int n_words) {
    int nz = 0;
    for (int i = threadIdx.x; i < 2048; i += 32) {
        int w = 2 * i + 1;
        if (w < n_words && ei[w] != 0) nz = 1;
    }
    nz = __any_sync(0xffffffffu, nz);
    if (threadIdx.x == 0) g_is64 = nz ? 0 : 1;
}

// ---------------------------------------------------------------------------
// zero: counters + BN stats + spill count (must run every graph replay)
// ---------------------------------------------------------------------------
__global__ void zero_kernel(int n_nodes) {
    int i = blockIdx.x * blockDim.x + threadIdx.x;
    if (i < n_nodes) g_cnt[i] = 0;
    if (i < 2 * F) g_stats[i] = 0.0f;
    if (i == 2 * F) g_nspill = 0;
}

// ---------------------------------------------------------------------------
// convert: unpack indices (guarded) + build padded CSR directly
// ---------------------------------------------------------------------------
__global__ void convert_kernel(const void* __restrict__ eiv, int n_edges,
                               int n_nodes) {
    int e = blockIdx.x * blockDim.x + threadIdx.x;
    if (e >= n_edges) return;
    long long s, d;
    if (g_is64) {
        const long long* ei = (const long long*)eiv;
        s = ei[e];
        d = ei[n_edges + e];
    } else {
        const int* ei = (const int*)eiv;
        s = ei[e];
        d = ei[n_edges + e];
    }
    if (s < 0 || s >= n_nodes || d < 0 || d >= n_nodes) return;
    int di = (int)d, si = (int)s;
    int c = atomicAdd(&g_cnt[di], 1);
    if (c < DEG_CAP) {
        g_csrp[di * DEG_CAP + c] = si;
    } else {
        int p = atomicAdd(&g_nspill, 1);
        if (p < SPILL_CAP) {
            g_spill[2 * p] = di;
            g_spill[2 * p + 1] = si;
        }
    }
}

// ---------------------------------------------------------------------------
// GEMM: out[m][n] = act( sum_k A[m][k] * W[n][k] + bias[n] )
// Mainloop uses packed fma.rn.f32x2 along K (even/odd partial sums).
// FIRST: A-tile gathered on the fly from padded CSR
//        (agg = x[m] + sum x[src]), ReLU + BN-stat accumulation, out = g_h.
// else:  A = g_h, W columns scaled by g_sc during smem load, bias = g_b2p,
//        out = d_out.
// ---------------------------------------------------------------------------
#define PITCH 132
#define GEMM_SMEM ((64 + 128) * PITCH * 4)

__device__ __forceinline__ void f4add(float4& a, const float4& b) {
    a.x += b.x; a.y += b.y; a.z += b.z; a.w += b.w;
}

template <bool FIRST>
__global__ void __launch_bounds__(256, 2)
gemm_kernel(const float* __restrict__ Xp, const float* __restrict__ Wp,
            const float* __restrict__ biasp, float* __restrict__ outp, int M) {
    extern __shared__ float smem[];
    float* As = smem;               // 64 x PITCH
    float* Ws = smem + 64 * PITCH;  // 128 x PITCH

    const float* bias = FIRST ? biasp : g_b2p;
    float* out        = FIRST ? g_h   : outp;

    int tid = threadIdx.x;
    int m0 = blockIdx.x * 64;
    int tx = tid & 31, ty = tid >> 5;

    // Load W (128x128), coalesced float4, store pitch-132.
    // Second layer: scale column k by g_sc[k] (BN fold) during the load.
#pragma unroll
    for (int p = 0; p < 16; p++) {
        int idx = tid + p * 256;            // float4 index
        int r = idx >> 5, c4 = idx & 31;
        float4 v = ((const float4*)Wp)[idx];
        if (!FIRST) {
            float4 sc = ((const float4*)g_sc)[c4];
            v.x *= sc.x; v.y *= sc.y; v.z *= sc.z; v.w *= sc.w;
        }
        *(float4*)&Ws[r * PITCH + c4 * 4] = v;
    }

    if (FIRST) {
        // Gather-aggregate from padded CSR: warp ty owns rows m0+ty*8 .. +7
        const float4* x4 = (const float4*)Xp;
        int nspill = g_nspill;
        if (nspill > SPILL_CAP) nspill = SPILL_CAP;
#pragma unroll 1
        for (int i = 0; i < 8; i++) {
            int r = ty * 8 + i;
            int m = m0 + r;
            float4 a0 = make_float4(0.f, 0.f, 0.f, 0.f);
            float4 a1 = a0, a2 = a0, a3 = a0;
            if (m < M) {
                a0 = __ldg(&x4[(size_t)m * 32 + tx]);   // self term
                int deg = g_cnt[m];
                int dc = deg < DEG_CAP ? deg : DEG_CAP;
                const int* lst = g_csrp + (size_t)m * DEG_CAP;
                int e = 0;
                for (; e + 3 < dc; e += 4) {
                    int s0 = __ldg(&lst[e]),     s1 = __ldg(&lst[e + 1]);
                    int s2 = __ldg(&lst[e + 2]), s3 = __ldg(&lst[e + 3]);
                    float4 v0 = __ldg(&x4[(size_t)s0 * 32 + tx]);
                    float4 v1 = __ldg(&x4[(size_t)s1 * 32 + tx]);
                    float4 v2 = __ldg(&x4[(size_t)s2 * 32 + tx]);
                    float4 v3 = __ldg(&x4[(size_t)s3 * 32 + tx]);
                    f4add(a0, v0); f4add(a1, v1); f4add(a2, v2); f4add(a3, v3);
                }
                for (; e < dc; e++)
                    f4add(a1, __ldg(&x4[(size_t)__ldg(&lst[e]) * 32 + tx]));
                if (deg > DEG_CAP) {        // spill path (normally never taken)
                    for (int q = 0; q < nspill; q++) {
                        if (g_spill[2 * q] == m)
                            f4add(a2, __ldg(&x4[(size_t)g_spill[2 * q + 1] * 32 + tx]));
                    }
                }
                f4add(a0, a1); f4add(a2, a3); f4add(a0, a2);
            }
            *(float4*)&As[r * PITCH + tx * 4] = a0;
        }
    } else {
        // Load A tile (64x128) from g_h
#pragma unroll
        for (int p = 0; p < 8; p++) {
            int idx = tid + p * 256;
            int r = idx >> 5, c4 = idx & 31;
            int m = m0 + r;
            float4 v = make_float4(0.f, 0.f, 0.f, 0.f);
            if (m < M) v = ((const float4*)g_h)[(size_t)m * 32 + c4];
            *(float4*)&As[r * PITCH + c4 * 4] = v;
        }
    }
    __syncthreads();

    // Accumulators: f32x2 packed {even-k partial, odd-k partial}
    unsigned long long acc[8][4];
#pragma unroll
    for (int i = 0; i < 8; i++)
#pragma unroll
        for (int j = 0; j < 4; j++) acc[i][j] = 0ull;

#pragma unroll 4
    for (int k4 = 0; k4 < 32; k4++) {
        ulonglong2 wv[4];   // {k,k+1} in .x, {k+2,k+3} in .y
#pragma unroll
        for (int j = 0; j < 4; j++)
            wv[j] = *(const ulonglong2*)&Ws[(tx + 32 * j) * PITCH + k4 * 4];
#pragma unroll
        for (int i = 0; i < 8; i++) {
            ulonglong2 av =
                *(const ulonglong2*)&As[(ty * 8 + i) * PITCH + k4 * 4];
#pragma unroll
            for (int j = 0; j < 4; j++) {
                ffma2(acc[i][j], av.x, wv[j].x);
                ffma2(acc[i][j], av.y, wv[j].y);
            }
        }
    }
    __syncthreads();  // smem reused below for stats reduction

    float b[4];
#pragma unroll
    for (int j = 0; j < 4; j++) b[j] = bias[tx + 32 * j];

    float colS[4] = {0.f, 0.f, 0.f, 0.f};
    float colQ[4] = {0.f, 0.f, 0.f, 0.f};
#pragma unroll
    for (int i = 0; i < 8; i++) {
        int m = m0 + ty * 8 + i;
        if (m < M) {
#pragma unroll
            for (int j = 0; j < 4; j++) {
                float v = f2sum(acc[i][j]) + b[j];
                if (FIRST) v = fmaxf(v, 0.0f);
                out[(size_t)m * F + tx + 32 * j] = v;
                if (FIRST) { colS[j] += v; colQ[j] += v * v; }
            }
        }
    }

    if (FIRST) {
        float* redS = smem;          // 8 x 128
        float* redQ = smem + 1024;   // 8 x 128
#pragma unroll
        for (int j = 0; j < 4; j++) {
            redS[ty * F + tx + 32 * j] = colS[j];
            redQ[ty * F + tx + 32 * j] = colQ[j];
        }
        __syncthreads();
        if (tid < F) {
            float s = 0.f;
#pragma unroll
            for (int t = 0; t < 8; t++) s += redS[t * F + tid];
            atomicAdd(&g_stats[tid], s);
        } else {
            int c = tid - F;
            float q = 0.f;
#pragma unroll
            for (int t = 0; t < 8; t++) q += redQ[t * F + c];
            atomicAdd(&g_stats[F + c], q);
        }
    }
}

// ---------------------------------------------------------------------------
// fold: s[k] = gamma*rsqrt(var+eps), t[k] = beta - mean*s
//   g_sc[k] = s[k]  (applied to W2 columns inside gemm2's W load)
//   g_b2p[o] = b2[o] + sum_k W2[o][k] * t[k]     (one block per row o)
// ---------------------------------------------------------------------------
__global__ void fold_kernel(const float* __restrict__ gamma,
                            const float* __restrict__ beta,
                            const float* __restrict__ W2,
                            const float* __restrict__ b2, float invM) {
    __shared__ float red[F];
    int o = blockIdx.x, t = threadIdx.x;  // 128 blocks x 128 threads
    float S = g_stats[t], Q = g_stats[F + t];
    float mean = S * invM;
    float var = Q * invM - mean * mean;
    float s = gamma[t] * rsqrtf(var + 1e-5f);
    float tc = beta[t] - mean * s;
    if (o == 0) g_sc[t] = s;
    red[t] = W2[o * F + t] * tc;
    __syncthreads();
#pragma unroll
    for (int off = 64; off > 0; off >>= 1) {
        if (t < off) red[t] += red[t + off];
        __syncthreads();
    }
    if (t == 0) g_b2p[o] = b2[o] + red[0];
}

// ---------------------------------------------------------------------------
extern "C" void kernel_launch(void* const* d_in, const int* in_sizes, int n_in,
                              void* d_out, int out_size) {
    const float* x         = (const float*)d_in[0];
    const void*  ei        = (const void*)d_in[1];
    const float* W1        = (const float*)d_in[2];
    const float* b1        = (const float*)d_in[3];
    const float* gamma     = (const float*)d_in[4];
    const float* beta      = (const float*)d_in[5];
    const float* W2        = (const float*)d_in[6];
    const float* b2        = (const float*)d_in[7];
    float* out             = (float*)d_out;

    int n_nodes = in_sizes[0] / F;
    int n_edges = in_sizes[1] / 2;

    cudaFuncSetAttribute(gemm_kernel<true>,
                         cudaFuncAttributeMaxDynamicSharedMemorySize, GEMM_SMEM);
    cudaFuncSetAttribute(gemm_kernel<false>,
                         cudaFuncAttributeMaxDynamicSharedMemorySize, GEMM_SMEM);

    detect_kernel<<<1, 32>>>((const int*)ei, in_sizes[1]);
    zero_kernel<<<(n_nodes + 255) / 256, 256>>>(n_nodes);
    convert_kernel<<<(n_edges + 255) / 256, 256>>>(ei, n_edges, n_nodes);

    int gb = (n_nodes + 63) / 64;
    gemm_kernel<true><<<gb, 256, GEMM_SMEM>>>(x, W1, b1, nullptr, n_nodes);
    fold_kernel<<<F, F>>>(gamma, beta, W2, b2, 1.0f / (float)n_nodes);
    gemm_kernel<false><<<gb, 256, GEMM_SMEM>>>(nullptr, W2, nullptr, out,
                                               n_nodes);
}

// round 7
// speedup vs baseline: 1.2324x; 1.1351x over previous
#include <cuda_runtime.h>
#include <cuda_bf16.h>

#define MAX_NODES 50000
#define MAX_E     800000
#define F 128
#define DEG_CAP   64
#define SPILL_CAP 65536

// Scratch (device globals; allocation-free per harness rules)
__device__ float g_agg[MAX_NODES * F];
__device__ float g_h[MAX_NODES * F];
__device__ float g_stats[2 * F];       // [0:128) sum, [128:256) sumsq
__device__ float g_sc[F];              // BN scale folded into W2 columns
__device__ float g_b2p[F];             // BN-folded bias for layer 2
__device__ int   g_cnt[MAX_NODES];     // degree per dst
__device__ int   g_csrp[MAX_NODES * DEG_CAP];  // padded CSR (12.8 MB)
__device__ int   g_spill[2 * SPILL_CAP];
__device__ int   g_nspill;
__device__ int   g_is64;

// packed f32x2 FMA: d = a*b + d  (even/odd K partial sums)
__device__ __forceinline__ void ffma2(unsigned long long& d,
                                      unsigned long long a,
                                      unsigned long long b) {
    asm("fma.rn.f32x2 %0, %1, %2, %0;" : "+l"(d) : "l"(a), "l"(b));
}
__device__ __forceinline__ float f2sum(unsigned long long p) {
    float lo = __int_as_float((int)(unsigned)(p & 0xffffffffull));
    float hi = __int_as_float((int)(unsigned)(p >> 32));
    return lo + hi;
}

// ---------------------------------------------------------------------------
// detect: edge_index int64 (all odd 32-bit words zero) vs int32
// ---------------------------------------------------------------------------
__global__ void detect_kernel(const int* __restrict__ ei, int n_words) {
    int nz = 0;
    for (int i = threadIdx.x; i < 2048; i += 32) {
        int w = 2 * i + 1;
        if (w < n_words && ei[w] != 0) nz = 1;
    }
    nz = __any_sync(0xffffffffu, nz);
    if (threadIdx.x == 0) g_is64 = nz ? 0 : 1;
}

// ---------------------------------------------------------------------------
// zero: counters + BN stats + spill count (must run every graph replay)
// ---------------------------------------------------------------------------
__global__ void zero_kernel(int n_nodes) {
    int i = blockIdx.x * blockDim.x + threadIdx.x;
    if (i < n_nodes) g_cnt[i] = 0;
    if (i < 2 * F) g_stats[i] = 0.0f;
    if (i == 2 * F) g_nspill = 0;
}

// ---------------------------------------------------------------------------
// convert: unpack indices (guarded) + build padded CSR directly
// ---------------------------------------------------------------------------
__global__ void convert_kernel(const void* __restrict__ eiv, int n_edges,
                               int n_nodes) {
    int e = blockIdx.x * blockDim.x + threadIdx.x;
    if (e >= n_edges) return;
    long long s, d;
    if (g_is64) {
        const long long* ei = (const long long*)eiv;
        s = ei[e];
        d = ei[n_edges + e];
    } else {
        const int* ei = (const int*)eiv;
        s = ei[e];
        d = ei[n_edges + e];
    }
    if (s < 0 || s >= n_nodes || d < 0 || d >= n_nodes) return;
    int di = (int)d, si = (int)s;
    int c = atomicAdd(&g_cnt[di], 1);
    if (c < DEG_CAP) {
        g_csrp[di * DEG_CAP + c] = si;
    } else {
        int p = atomicAdd(&g_nspill, 1);
        if (p < SPILL_CAP) {
            g_spill[2 * p] = di;
            g_spill[2 * p + 1] = si;
        }
    }
}

// ---------------------------------------------------------------------------
// gather: agg[m] = x[m] + sum_{src in CSR[m]} x[src]; one warp per node.
// No smem, low regs -> high occupancy; MLP=4 dependent-load groups.
// ---------------------------------------------------------------------------
__device__ __forceinline__ void f4add(float4& a, const float4& b) {
    a.x += b.x; a.y += b.y; a.z += b.z; a.w += b.w;
}

__global__ void __launch_bounds__(256)
gather_kernel(const float* __restrict__ Xp, int n_nodes) {
    int m = (blockIdx.x * blockDim.x + threadIdx.x) >> 5;
    int tx = threadIdx.x & 31;
    if (m >= n_nodes) return;
    const float4* x4 = (const float4*)Xp;

    float4 a0 = __ldg(&x4[(size_t)m * 32 + tx]);   // self term
    float4 a1 = make_float4(0.f, 0.f, 0.f, 0.f);
    float4 a2 = a1, a3 = a1;

    int deg = g_cnt[m];
    int dc = deg < DEG_CAP ? deg : DEG_CAP;
    const int* lst = g_csrp + (size_t)m * DEG_CAP;
    int e = 0;
    for (; e + 3 < dc; e += 4) {
        int s0 = __ldg(&lst[e]),     s1 = __ldg(&lst[e + 1]);
        int s2 = __ldg(&lst[e + 2]), s3 = __ldg(&lst[e + 3]);
        float4 v0 = __ldg(&x4[(size_t)s0 * 32 + tx]);
        float4 v1 = __ldg(&x4[(size_t)s1 * 32 + tx]);
        float4 v2 = __ldg(&x4[(size_t)s2 * 32 + tx]);
        float4 v3 = __ldg(&x4[(size_t)s3 * 32 + tx]);
        f4add(a0, v0); f4add(a1, v1); f4add(a2, v2); f4add(a3, v3);
    }
    for (; e < dc; e++)
        f4add(a1, __ldg(&x4[(size_t)__ldg(&lst[e]) * 32 + tx]));
    if (deg > DEG_CAP) {                 // spill path (normally never taken)
        int nspill = g_nspill;
        if (nspill > SPILL_CAP) nspill = SPILL_CAP;
        for (int q = 0; q < nspill; q++)
            if (g_spill[2 * q] == m)
                f4add(a2, __ldg(&x4[(size_t)g_spill[2 * q + 1] * 32 + tx]));
    }
    f4add(a0, a1); f4add(a2, a3); f4add(a0, a2);
    ((float4*)g_agg)[(size_t)m * 32 + tx] = a0;
}

// ---------------------------------------------------------------------------
// GEMM: out[m][n] = act( sum_k A[m][k] * W[n][k] + bias[n] )
// Mainloop uses packed fma.rn.f32x2 along K (even/odd partial sums).
// FIRST: A = g_agg, ReLU + BN-stat accumulation, out = g_h.
// else:  A = g_h, W columns scaled by g_sc during smem load, bias = g_b2p,
//        out = d_out.
// ---------------------------------------------------------------------------
#define PITCH 132
#define GEMM_SMEM ((64 + 128) * PITCH * 4)

template <bool FIRST>
__global__ void __launch_bounds__(256, 2)
gemm_kernel(const float* __restrict__ Wp, const float* __restrict__ biasp,
            float* __restrict__ outp, int M) {
    extern __shared__ float smem[];
    float* As = smem;               // 64 x PITCH
    float* Ws = smem + 64 * PITCH;  // 128 x PITCH

    const float* A    = FIRST ? g_agg : g_h;
    const float* bias = FIRST ? biasp : g_b2p;
    float* out        = FIRST ? g_h   : outp;

    int tid = threadIdx.x;
    int m0 = blockIdx.x * 64;
    int tx = tid & 31, ty = tid >> 5;

    // Load W (128x128), coalesced float4, store pitch-132.
    // Second layer: scale column k by g_sc[k] (BN fold) during the load.
#pragma unroll
    for (int p = 0; p < 16; p++) {
        int idx = tid + p * 256;            // float4 index
        int r = idx >> 5, c4 = idx & 31;
        float4 v = ((const float4*)Wp)[idx];
        if (!FIRST) {
            float4 sc = ((const float4*)g_sc)[c4];
            v.x *= sc.x; v.y *= sc.y; v.z *= sc.z; v.w *= sc.w;
        }
        *(float4*)&Ws[r * PITCH + c4 * 4] = v;
    }

    // Load A tile (64x128), coalesced float4
#pragma unroll
    for (int p = 0; p < 8; p++) {
        int idx = tid + p * 256;
        int r = idx >> 5, c4 = idx & 31;
        int m = m0 + r;
        float4 v = make_float4(0.f, 0.f, 0.f, 0.f);
        if (m < M) v = ((const float4*)A)[(size_t)m * 32 + c4];
        *(float4*)&As[r * PITCH + c4 * 4] = v;
    }
    __syncthreads();

    // Accumulators: f32x2 packed {even-k partial, odd-k partial}
    unsigned long long acc[8][4];
#pragma unroll
    for (int i = 0; i < 8; i++)
#pragma unroll
        for (int j = 0; j < 4; j++) acc[i][j] = 0ull;

#pragma unroll 4
    for (int k4 = 0; k4 < 32; k4++) {
        ulonglong2 wv[4];   // {k,k+1} in .x, {k+2,k+3} in .y
#pragma unroll
        for (int j = 0; j < 4; j++)
            wv[j] = *(const ulonglong2*)&Ws[(tx + 32 * j) * PITCH + k4 * 4];
#pragma unroll
        for (int i = 0; i < 8; i++) {
            ulonglong2 av =
                *(const ulonglong2*)&As[(ty * 8 + i) * PITCH + k4 * 4];
#pragma unroll
            for (int j = 0; j < 4; j++) {
                ffma2(acc[i][j], av.x, wv[j].x);
                ffma2(acc[i][j], av.y, wv[j].y);
            }
        }
    }
    __syncthreads();  // smem reused below for stats reduction

    float b[4];
#pragma unroll
    for (int j = 0; j < 4; j++) b[j] = bias[tx + 32 * j];

    float colS[4] = {0.f, 0.f, 0.f, 0.f};
    float colQ[4] = {0.f, 0.f, 0.f, 0.f};
#pragma unroll
    for (int i = 0; i < 8; i++) {
        int m = m0 + ty * 8 + i;
        if (m < M) {
#pragma unroll
            for (int j = 0; j < 4; j++) {
                float v = f2sum(acc[i][j]) + b[j];
                if (FIRST) v = fmaxf(v, 0.0f);
                out[(size_t)m * F + tx + 32 * j] = v;
                if (FIRST) { colS[j] += v; colQ[j] += v * v; }
            }
        }
    }

    if (FIRST) {
        float* redS = smem;          // 8 x 128
        float* redQ = smem + 1024;   // 8 x 128
#pragma unroll
        for (int j = 0; j < 4; j++) {
            redS[ty * F + tx + 32 * j] = colS[j];
            redQ[ty * F + tx + 32 * j] = colQ[j];
        }
        __syncthreads();
        if (tid < F) {
            float s = 0.f;
#pragma unroll
            for (int t = 0; t < 8; t++) s += redS[t * F + tid];
            atomicAdd(&g_stats[tid], s);
        } else {
            int c = tid - F;
            float q = 0.f;
#pragma unroll
            for (int t = 0; t < 8; t++) q += redQ[t * F + c];
            atomicAdd(&g_stats[F + c], q);
        }
    }
}

// ---------------------------------------------------------------------------
// fold: s[k] = gamma*rsqrt(var+eps), t[k] = beta - mean*s
//   g_sc[k] = s[k]  (applied to W2 columns inside gemm2's W load)
//   g_b2p[o] = b2[o] + sum_k W2[o][k] * t[k]     (one block per row o)
// ---------------------------------------------------------------------------
__global__ void fold_kernel(const float* __restrict__ gamma,
                            const float* __restrict__ beta,
                            const float* __restrict__ W2,
                            const float* __restrict__ b2, float invM) {
    __shared__ float red[F];
    int o = blockIdx.x, t = threadIdx.x;  // 128 blocks x 128 threads
    float S = g_stats[t], Q = g_stats[F + t];
    float mean = S * invM;
    float var = Q * invM - mean * mean;
    float s = gamma[t] * rsqrtf(var + 1e-5f);
    float tc = beta[t] - mean * s;
    if (o == 0) g_sc[t] = s;
    red[t] = W2[o * F + t] * tc;
    __syncthreads();
#pragma unroll
    for (int off = 64; off > 0; off >>= 1) {
        if (t < off) red[t] += red[t + off];
        __syncthreads();
    }
    if (t == 0) g_b2p[o] = b2[o] + red[0];
}

// ---------------------------------------------------------------------------
extern "C" void kernel_launch(void* const* d_in, const int* in_sizes, int n_in,
                              void* d_out, int out_size) {
    const float* x         = (const float*)d_in[0];
    const void*  ei        = (const void*)d_in[1];
    const float* W1        = (const float*)d_in[2];
    const float* b1        = (const float*)d_in[3];
    const float* gamma     = (const float*)d_in[4];
    const float* beta      = (const float*)d_in[5];
    const float* W2        = (const float*)d_in[6];
    const float* b2        = (const float*)d_in[7];
    float* out             = (float*)d_out;

    int n_nodes = in_sizes[0] / F;
    int n_edges = in_sizes[1] / 2;

    cudaFuncSetAttribute(gemm_kernel<true>,
                         cudaFuncAttributeMaxDynamicSharedMemorySize, GEMM_SMEM);
    cudaFuncSetAttribute(gemm_kernel<false>,
                         cudaFuncAttributeMaxDynamicSharedMemorySize, GEMM_SMEM);

    detect_kernel<<<1, 32>>>((const int*)ei, in_sizes[1]);
    zero_kernel<<<(n_nodes + 255) / 256, 256>>>(n_nodes);
    convert_kernel<<<(n_edges + 255) / 256, 256>>>(ei, n_edges, n_nodes);

    int gwarps_blocks = (n_nodes * 32 + 255) / 256;
    gather_kernel<<<gwarps_blocks, 256>>>(x, n_nodes);

    int gb = (n_nodes + 63) / 64;
    gemm_kernel<true><<<gb, 256, GEMM_SMEM>>>(W1, b1, nullptr, n_nodes);
    fold_kernel<<<F, F>>>(gamma, beta, W2, b2, 1.0f / (float)n_nodes);
    gemm_kernel<false><<<gb, 256, GEMM_SMEM>>>(W2, nullptr, out, n_nodes);
}

// round 8
// speedup vs baseline: 1.8066x; 1.4660x over previous
#include <cuda_runtime.h>
#include <cuda_bf16.h>

#define MAX_NODES 50000
#define MAX_E     800000
#define F 128
#define DEG_CAP   64
#define SPILL_CAP 65536

// Scratch (device globals; allocation-free per harness rules)
__device__ float g_agg[MAX_NODES * F];
__device__ float g_h[MAX_NODES * F];
__device__ float g_stats[2 * F];       // [0:128) sum, [128:256) sumsq
__device__ float g_sc[F];              // BN scale folded into W2 columns
__device__ float g_b2p[F];             // BN-folded bias for layer 2
__device__ int   g_cnt[MAX_NODES];     // degree per dst
__device__ int   g_csrp[MAX_NODES * DEG_CAP];  // padded CSR (12.8 MB)
__device__ int   g_spill[2 * SPILL_CAP];
__device__ int   g_nspill;
__device__ int   g_is64;

// ---------------------------------------------------------------------------
// tf32 helpers
// ---------------------------------------------------------------------------
__device__ __forceinline__ unsigned tf32r(float f) {
    unsigned u;
    asm("cvt.rna.tf32.f32 %0, %1;" : "=r"(u) : "f"(f));
    return u;
}
__device__ __forceinline__ void mma_tf32(
    float& d0, float& d1, float& d2, float& d3,
    unsigned a0, unsigned a1, unsigned a2, unsigned a3,
    unsigned b0, unsigned b1) {
    asm volatile(
        "mma.sync.aligned.m16n8k8.row.col.f32.tf32.tf32.f32 "
        "{%0,%1,%2,%3},{%4,%5,%6,%7},{%8,%9},{%0,%1,%2,%3};"
        : "+f"(d0), "+f"(d1), "+f"(d2), "+f"(d3)
        : "r"(a0), "r"(a1), "r"(a2), "r"(a3), "r"(b0), "r"(b1));
}

// ---------------------------------------------------------------------------
// detect: edge_index int64 (all odd 32-bit words zero) vs int32
// ---------------------------------------------------------------------------
__global__ void detect_kernel(const int* __restrict__ ei, int n_words) {
    int nz = 0;
    for (int i = threadIdx.x; i < 2048; i += 32) {
        int w = 2 * i + 1;
        if (w < n_words && ei[w] != 0) nz = 1;
    }
    nz = __any_sync(0xffffffffu, nz);
    if (threadIdx.x == 0) g_is64 = nz ? 0 : 1;
}

// ---------------------------------------------------------------------------
// zero: counters + BN stats + spill count (must run every graph replay)
// ---------------------------------------------------------------------------
__global__ void zero_kernel(int n_nodes) {
    int i = blockIdx.x * blockDim.x + threadIdx.x;
    if (i < n_nodes) g_cnt[i] = 0;
    if (i < 2 * F) g_stats[i] = 0.0f;
    if (i == 2 * F) g_nspill = 0;
}

// ---------------------------------------------------------------------------
// convert: unpack indices (guarded) + build padded CSR directly
// ---------------------------------------------------------------------------
__global__ void convert_kernel(const void* __restrict__ eiv, int n_edges,
                               int n_nodes) {
    int e = blockIdx.x * blockDim.x + threadIdx.x;
    if (e >= n_edges) return;
    long long s, d;
    if (g_is64) {
        const long long* ei = (const long long*)eiv;
        s = ei[e];
        d = ei[n_edges + e];
    } else {
        const int* ei = (const int*)eiv;
        s = ei[e];
        d = ei[n_edges + e];
    }
    if (s < 0 || s >= n_nodes || d < 0 || d >= n_nodes) return;
    int di = (int)d, si = (int)s;
    int c = atomicAdd(&g_cnt[di], 1);
    if (c < DEG_CAP) {
        g_csrp[di * DEG_CAP + c] = si;
    } else {
        int p = atomicAdd(&g_nspill, 1);
        if (p < SPILL_CAP) {
            g_spill[2 * p] = di;
            g_spill[2 * p + 1] = si;
        }
    }
}

// ---------------------------------------------------------------------------
// gather: agg[m] = x[m] + sum_{src in CSR[m]} x[src]; one warp per node.
// ---------------------------------------------------------------------------
__device__ __forceinline__ void f4add(float4& a, const float4& b) {
    a.x += b.x; a.y += b.y; a.z += b.z; a.w += b.w;
}

__global__ void __launch_bounds__(256)
gather_kernel(const float* __restrict__ Xp, int n_nodes) {
    int m = (blockIdx.x * blockDim.x + threadIdx.x) >> 5;
    int tx = threadIdx.x & 31;
    if (m >= n_nodes) return;
    const float4* x4 = (const float4*)Xp;

    float4 a0 = __ldg(&x4[(size_t)m * 32 + tx]);   // self term
    float4 a1 = make_float4(0.f, 0.f, 0.f, 0.f);
    float4 a2 = a1, a3 = a1;

    int deg = g_cnt[m];
    int dc = deg < DEG_CAP ? deg : DEG_CAP;
    const int* lst = g_csrp + (size_t)m * DEG_CAP;
    int e = 0;
    for (; e + 3 < dc; e += 4) {
        int s0 = __ldg(&lst[e]),     s1 = __ldg(&lst[e + 1]);
        int s2 = __ldg(&lst[e + 2]), s3 = __ldg(&lst[e + 3]);
        float4 v0 = __ldg(&x4[(size_t)s0 * 32 + tx]);
        float4 v1 = __ldg(&x4[(size_t)s1 * 32 + tx]);
        float4 v2 = __ldg(&x4[(size_t)s2 * 32 + tx]);
        float4 v3 = __ldg(&x4[(size_t)s3 * 32 + tx]);
        f4add(a0, v0); f4add(a1, v1); f4add(a2, v2); f4add(a3, v3);
    }
    for (; e < dc; e++)
        f4add(a1, __ldg(&x4[(size_t)__ldg(&lst[e]) * 32 + tx]));
    if (deg > DEG_CAP) {                 // spill path (normally never taken)
        int nspill = g_nspill;
        if (nspill > SPILL_CAP) nspill = SPILL_CAP;
        for (int q = 0; q < nspill; q++)
            if (g_spill[2 * q] == m)
                f4add(a2, __ldg(&x4[(size_t)g_spill[2 * q + 1] * 32 + tx]));
    }
    f4add(a0, a1); f4add(a2, a3); f4add(a0, a2);
    ((float4*)g_agg)[(size_t)m * 32 + tx] = a0;
}

// ---------------------------------------------------------------------------
// Tensor-core GEMM (tf32 mma.sync): out[m][n] = act(sum_k A[m][k]*W[n][k] + b)
// Block: 256 thr = 8 warps as (wy 2) x (wx 4); tile 64(m) x 128(n), K=128.
// Warp tile 32x32 = 2 m-subtiles (16) x 4 n-subtiles (8); 16 k-steps of 8.
// Operands rounded to tf32 once, at smem tile store.
// FIRST: A=g_agg, ReLU + BN stats, out=g_h.
// else:  A=g_h, W cols scaled by g_sc, bias=g_b2p, out=d_out.
// ---------------------------------------------------------------------------
#define PITCH 132
#define GEMM_SMEM ((64 + 128) * PITCH * 4)

template <bool FIRST>
__global__ void __launch_bounds__(256, 2)
gemm_kernel(const float* __restrict__ Wp, const float* __restrict__ biasp,
            float* __restrict__ outp, int M) {
    extern __shared__ float smem[];
    float* As = smem;               // 64 x PITCH (tf32-rounded)
    float* Ws = smem + 64 * PITCH;  // 128 x PITCH (tf32-rounded)

    const float* A    = FIRST ? g_agg : g_h;
    const float* bias = FIRST ? biasp : g_b2p;
    float* out        = FIRST ? g_h   : outp;

    int tid = threadIdx.x;
    int lane = tid & 31, wid = tid >> 5;
    int g = lane >> 2, tig = lane & 3;
    int wy = wid & 1, wx = wid >> 1;
    int m0 = blockIdx.x * 64;

    // Load W (128x128), coalesced float4, tf32-round, store pitch-132.
#pragma unroll
    for (int p = 0; p < 16; p++) {
        int idx = tid + p * 256;            // float4 index
        int r = idx >> 5, c4 = idx & 31;
        float4 v = ((const float4*)Wp)[idx];
        if (!FIRST) {
            float4 sc = ((const float4*)g_sc)[c4];
            v.x *= sc.x; v.y *= sc.y; v.z *= sc.z; v.w *= sc.w;
        }
        uint4 u = make_uint4(tf32r(v.x), tf32r(v.y), tf32r(v.z), tf32r(v.w));
        *(uint4*)&Ws[r * PITCH + c4 * 4] = u;
    }
    // Load A tile (64x128), tf32-round
#pragma unroll
    for (int p = 0; p < 8; p++) {
        int idx = tid + p * 256;
        int r = idx >> 5, c4 = idx & 31;
        int m = m0 + r;
        float4 v = make_float4(0.f, 0.f, 0.f, 0.f);
        if (m < M) v = ((const float4*)A)[(size_t)m * 32 + c4];
        uint4 u = make_uint4(tf32r(v.x), tf32r(v.y), tf32r(v.z), tf32r(v.w));
        *(uint4*)&As[r * PITCH + c4 * 4] = u;
    }
    __syncthreads();

    float d[2][4][4];
#pragma unroll
    for (int mi = 0; mi < 2; mi++)
#pragma unroll
        for (int ni = 0; ni < 4; ni++)
#pragma unroll
            for (int j = 0; j < 4; j++) d[mi][ni][j] = 0.0f;

    const float* Ab = As + (wy * 32) * PITCH;
    const float* Bb = Ws + (wx * 32) * PITCH;

#pragma unroll
    for (int kk = 0; kk < 16; kk++) {
        int kc = kk * 8;
        unsigned a[2][4];
#pragma unroll
        for (int mi = 0; mi < 2; mi++) {
            const float* ap = Ab + (mi * 16 + g) * PITCH + kc + tig;
            a[mi][0] = __float_as_uint(ap[0]);
            a[mi][1] = __float_as_uint(ap[8 * PITCH]);
            a[mi][2] = __float_as_uint(ap[4]);
            a[mi][3] = __float_as_uint(ap[8 * PITCH + 4]);
        }
        unsigned b[4][2];
#pragma unroll
        for (int ni = 0; ni < 4; ni++) {
            const float* bp = Bb + (ni * 8 + g) * PITCH + kc + tig;
            b[ni][0] = __float_as_uint(bp[0]);
            b[ni][1] = __float_as_uint(bp[4]);
        }
#pragma unroll
        for (int mi = 0; mi < 2; mi++)
#pragma unroll
            for (int ni = 0; ni < 4; ni++)
                mma_tf32(d[mi][ni][0], d[mi][ni][1], d[mi][ni][2], d[mi][ni][3],
                         a[mi][0], a[mi][1], a[mi][2], a[mi][3],
                         b[ni][0], b[ni][1]);
    }
    __syncthreads();  // smem (As region) reused for stats staging below

    // Epilogue: bias (+ReLU+stats for FIRST), write out.
    // Thread covers cols c(ni)=wx*32+ni*8+2*tig (+0,+1); rows per mi: r0,r0+8.
    float pS[4][2], pQ[4][2];
#pragma unroll
    for (int ni = 0; ni < 4; ni++) {
        pS[ni][0] = pS[ni][1] = 0.f;
        pQ[ni][0] = pQ[ni][1] = 0.f;
    }
#pragma unroll
    for (int mi = 0; mi < 2; mi++) {
        int r0 = m0 + wy * 32 + mi * 16 + g;
        int r1 = r0 + 8;
#pragma unroll
        for (int ni = 0; ni < 4; ni++) {
            int c = wx * 32 + ni * 8 + 2 * tig;
            float b0 = bias[c], b1 = bias[c + 1];
            if (r0 < M) {
                float v0 = d[mi][ni][0] + b0;
                float v1 = d[mi][ni][1] + b1;
                if (FIRST) { v0 = fmaxf(v0, 0.f); v1 = fmaxf(v1, 0.f); }
                *(float2*)&out[(size_t)r0 * F + c] = make_float2(v0, v1);
                if (FIRST) {
                    pS[ni][0] += v0; pS[ni][1] += v1;
                    pQ[ni][0] += v0 * v0; pQ[ni][1] += v1 * v1;
                }
            }
            if (r1 < M) {
                float v0 = d[mi][ni][2] + b0;
                float v1 = d[mi][ni][3] + b1;
                if (FIRST) { v0 = fmaxf(v0, 0.f); v1 = fmaxf(v1, 0.f); }
                *(float2*)&out[(size_t)r1 * F + c] = make_float2(v0, v1);
                if (FIRST) {
                    pS[ni][0] += v0; pS[ni][1] += v1;
                    pQ[ni][0] += v0 * v0; pQ[ni][1] += v1 * v1;
                }
            }
        }
    }

    if (FIRST) {
        // Reduce over g (lanes differing in bits 2..4) via shfl, then stage
        // per-(wy,col) partials in smem, then 256 global atomics.
#pragma unroll
        for (int ni = 0; ni < 4; ni++)
#pragma unroll
            for (int j = 0; j < 2; j++) {
#pragma unroll
                for (int mask = 4; mask <= 16; mask <<= 1) {
                    pS[ni][j] += __shfl_xor_sync(0xffffffffu, pS[ni][j], mask);
                    pQ[ni][j] += __shfl_xor_sync(0xffffffffu, pQ[ni][j], mask);
                }
            }
        float* sS = smem;          // [2][128]
        float* sQ = smem + 256;    // [2][128]
        if (g == 0) {
#pragma unroll
            for (int ni = 0; ni < 4; ni++) {
                int c = wx * 32 + ni * 8 + 2 * tig;
                sS[wy * F + c]     = pS[ni][0];
                sS[wy * F + c + 1] = pS[ni][1];
                sQ[wy * F + c]     = pQ[ni][0];
                sQ[wy * F + c + 1] = pQ[ni][1];
            }
        }
        __syncthreads();
        if (tid < F)
            atomicAdd(&g_stats[tid], sS[tid] + sS[F + tid]);
        else if (tid < 2 * F) {
            int c = tid - F;
            atomicAdd(&g_stats[F + c], sQ[c] + sQ[F + c]);
        }
    }
}

// ---------------------------------------------------------------------------
// fold: s[k] = gamma*rsqrt(var+eps), t[k] = beta - mean*s
//   g_sc[k] = s[k]  (applied to W2 columns inside gemm2's W load)
//   g_b2p[o] = b2[o] + sum_k W2[o][k] * t[k]     (one block per row o)
// ---------------------------------------------------------------------------
__global__ void fold_kernel(const float* __restrict__ gamma,
                            const float* __restrict__ beta,
                            const float* __restrict__ W2,
                            const float* __restrict__ b2, float invM) {
    __shared__ float red[F];
    int o = blockIdx.x, t = threadIdx.x;  // 128 blocks x 128 threads
    float S = g_stats[t], Q = g_stats[F + t];
    float mean = S * invM;
    float var = Q * invM - mean * mean;
    float s = gamma[t] * rsqrtf(var + 1e-5f);
    float tc = beta[t] - mean * s;
    if (o == 0) g_sc[t] = s;
    red[t] = W2[o * F + t] * tc;
    __syncthreads();
#pragma unroll
    for (int off = 64; off > 0; off >>= 1) {
        if (t < off) red[t] += red[t + off];
        __syncthreads();
    }
    if (t == 0) g_b2p[o] = b2[o] + red[0];
}

// ---------------------------------------------------------------------------
extern "C" void kernel_launch(void* const* d_in, const int* in_sizes, int n_in,
                              void* d_out, int out_size) {
    const float* x         = (const float*)d_in[0];
    const void*  ei        = (const void*)d_in[1];
    const float* W1        = (const float*)d_in[2];
    const float* b1        = (const float*)d_in[3];
    const float* gamma     = (const float*)d_in[4];
    const float* beta      = (const float*)d_in[5];
    const float* W2        = (const float*)d_in[6];
    const float* b2        = (const float*)d_in[7];
    float* out             = (float*)d_out;

    int n_nodes = in_sizes[0] / F;
    int n_edges = in_sizes[1] / 2;

    cudaFuncSetAttribute(gemm_kernel<true>,
                         cudaFuncAttributeMaxDynamicSharedMemorySize, GEMM_SMEM);
    cudaFuncSetAttribute(gemm_kernel<false>,
                         cudaFuncAttributeMaxDynamicSharedMemorySize, GEMM_SMEM);

    detect_kernel<<<1, 32>>>((const int*)ei, in_sizes[1]);
    zero_kernel<<<(n_nodes + 255) / 256, 256>>>(n_nodes);
    convert_kernel<<<(n_edges + 255) / 256, 256>>>(ei, n_edges, n_nodes);

    int gwarps_blocks = (n_nodes * 32 + 255) / 256;
    gather_kernel<<<gwarps_blocks, 256>>>(x, n_nodes);

    int gb = (n_nodes + 63) / 64;
    gemm_kernel<true><<<gb, 256, GEMM_SMEM>>>(W1, b1, nullptr, n_nodes);
    fold_kernel<<<F, F>>>(gamma, beta, W2, b2, 1.0f / (float)n_nodes);
    gemm_kernel<false><<<gb, 256, GEMM_SMEM>>>(W2, nullptr, out, n_nodes);
}